// round 12
// baseline (speedup 1.0000x reference)
#include <cuda_runtime.h>
#include <cuda_fp16.h>
#include <cstdint>
#include <cstddef>

#define D_TONES 88
#define DPAD    104
#define T_LEN   512
#define K2ST    256
#define BATCH   1024
#define TILE_T  64
#define NTILES  8

// ---------------- device scratch ----------------
__device__ __align__(16) __half g_wdh[K2ST * DPAD];   // fp16 weights [k][d] (pad zeroed)
__device__ float g_cst[K2ST];                         // sum_d log1mp
__device__ float g_a0[K2ST];                          // linear init w_init*x_init
__device__ __align__(16) __half g_seqh[(size_t)BATCH * T_LEN * D_TONES]; // fp16 gathered seq
// E in k2-fragment-permuted layout: [b][t][lane][uint4 = (a0,a1,a2,a3)]
// even t: normal orientation fragment; odd t: transposed orientation fragment
__device__ __align__(16) unsigned g_Ep[(size_t)BATCH * T_LEN * 128];
__device__ float g_msum4[BATCH * 4];
__device__ float g_C[BATCH];

// smem layout offsets for k1f (bytes)
#define SM_B    0                        // 256 x 104 half = 53248
#define SM_A    53248                    // 2 x 64 x 104 half = 26624
#define SM_CST  79872                    // 256 f32 = 1024
#define SM_RMX  80896                    // 4 x 2 x 16 f32 = 512
#define SM_WSUM 81408                    // 8 f32 = 32
#define SM_STG  81440                    // 32 rows x 132 words x 4B = 16896
#define SM_TOT  98336

#define SWZ(wd) ((wd) ^ (((wd) >> 3) & 4))

// ---------------- helpers ----------------
__device__ __forceinline__ unsigned smem_u32(const void* p) {
    return (unsigned)__cvta_generic_to_shared(p);
}
#define CP_ASYNC16(dst, src) \
    asm volatile("cp.async.cg.shared.global [%0], [%1], 16;" :: "r"(dst), "l"(src))
#define CP_COMMIT() asm volatile("cp.async.commit_group;")
#define CP_WAIT1()  asm volatile("cp.async.wait_group 1;")

__device__ __forceinline__ float warpSumf(float v) {
#pragma unroll
    for (int s = 16; s > 0; s >>= 1) v += __shfl_xor_sync(0xffffffffu, v, s);
    return v;
}
// warp sum via integer redux (fixed point, scale 32) — approximate kappa is fine,
// since the APPLIED kappa is exactly bookkept via lk.
__device__ __forceinline__ float warpSumRedux(float v) {
    unsigned pi = __float2uint_rn(fmaxf(v, 0.0f) * 32.0f);
    unsigned si;
    asm volatile("redux.sync.add.u32 %0, %1, 0xffffffff;" : "=r"(si) : "r"(pi));
    return __uint2float_rn(si) * 0.03125f;
}
__device__ __forceinline__ unsigned packh2(float lo, float hi) {
    __half2 h = __floats2half2_rn(lo, hi);
    return *reinterpret_cast<unsigned*>(&h);
}
__device__ __forceinline__ __half2 u2h(unsigned u) { return *reinterpret_cast<__half2*>(&u); }
__device__ __forceinline__ unsigned h2u(__half2 h) { return *reinterpret_cast<unsigned*>(&h); }
__device__ __forceinline__ unsigned movmT(unsigned s) {
    unsigned d;
    asm("movmatrix.sync.aligned.m8n8.trans.b16 %0,%1;" : "=r"(d) : "r"(s));
    return d;
}
// f32-accum mma (k1f emission GEMM)
__device__ __forceinline__ void mma16816(float d[4], const unsigned a[4],
                                         unsigned b0, unsigned b1) {
    asm volatile("mma.sync.aligned.m16n8k16.row.col.f32.f16.f16.f32 "
                 "{%0,%1,%2,%3},{%4,%5,%6,%7},{%8,%9},{%10,%11,%12,%13};"
                 : "=f"(d[0]), "=f"(d[1]), "=f"(d[2]), "=f"(d[3])
                 : "r"(a[0]), "r"(a[1]), "r"(a[2]), "r"(a[3]), "r"(b0), "r"(b1),
                   "f"(0.0f), "f"(0.0f), "f"(0.0f), "f"(0.0f));
}
// f16-accum mma (k2 recursion): C fragment layout == A fragment layout
__device__ __forceinline__ void mma_h16(unsigned& d0, unsigned& d1, const unsigned a[4],
                                        unsigned b0, unsigned b1) {
    asm volatile("mma.sync.aligned.m16n8k16.row.col.f16.f16.f16.f16 "
                 "{%0,%1},{%2,%3,%4,%5},{%6,%7},{%8,%9};"
                 : "=r"(d0), "=r"(d1)
                 : "r"(a[0]), "r"(a[1]), "r"(a[2]), "r"(a[3]), "r"(b0), "r"(b1),
                   "r"(0u), "r"(0u));
}

// one recursion step (f16 carry, orientation alternation, lagged kappa folded into E):
//   U = Z*M (f16 out) ; Ut = movm(U) ; Z' = (Ut*N) ⊙ (E*kappa)
// chain: mma -> movm -> mma -> hmul   (no packs, one movm group)
__device__ __forceinline__ void stepZ_h(unsigned Z[4], float& C, const uint4 E,
                                        const unsigned M[4], const unsigned N[4],
                                        __half2& kap2, float& lk) {
    __half2 hs = __hadd2(__hadd2(u2h(Z[0]), u2h(Z[1])), __hadd2(u2h(Z[2]), u2h(Z[3])));
    float2 fs = __half22float2(hs);
    float s = warpSumRedux(fs.x + fs.y);

    __half2 ek0 = __hmul2(u2h(E.x), kap2);
    __half2 ek1 = __hmul2(u2h(E.y), kap2);
    __half2 ek2 = __hmul2(u2h(E.z), kap2);
    __half2 ek3 = __hmul2(u2h(E.w), kap2);
    C -= lk;

    unsigned ul0, ul1, uh0, uh1;
    mma_h16(ul0, ul1, Z, M[0], M[1]);
    mma_h16(uh0, uh1, Z, M[2], M[3]);
    unsigned Ut[4];
    Ut[0] = movmT(ul0);
    Ut[1] = movmT(uh0);
    Ut[2] = movmT(ul1);
    Ut[3] = movmT(uh1);
    unsigned zl0, zl1, zh0, zh1;
    mma_h16(zl0, zl1, Ut, N[0], N[1]);
    mma_h16(zh0, zh1, Ut, N[2], N[3]);
    Z[0] = h2u(__hmul2(u2h(zl0), ek0));
    Z[1] = h2u(__hmul2(u2h(zl1), ek1));
    Z[2] = h2u(__hmul2(u2h(zh0), ek2));
    Z[3] = h2u(__hmul2(u2h(zh1), ek3));

    float kap = fminf(__fdividef(1024.0f, fmaxf(s, 1e-30f)), 60000.0f);
    __half kh = __float2half_rn(kap);
    kap2 = __half2half2(kh);
    lk = __logf(__half2float(kh));
}

// ---------------- K0: precompute (parallel: block per state k) ----------------
__global__ void __launch_bounds__(128) k0_setup(const float* __restrict__ probs_y,
                                                const float* __restrict__ w_init,
                                                const float* __restrict__ x_init) {
    __shared__ float red[4];
    const int k = blockIdx.x;
    const int d = threadIdx.x;
    float cs = 0.0f;
    if (d < D_TONES) {
        float py = __ldg(&probs_y[k * D_TONES + d]);
        float l1 = log1pf(-py);
        g_wdh[k * DPAD + d] = __float2half_rn(logf(py) - l1);
        cs = l1;
    } else if (d < DPAD) {
        g_wdh[k * DPAD + d] = __float2half_rn(0.0f);
    }
    cs = warpSumf(cs);
    if ((threadIdx.x & 31) == 0) red[threadIdx.x >> 5] = cs;
    __syncthreads();
    if (threadIdx.x == 0) {
        g_cst[k] = (red[0] + red[1]) + (red[2] + red[3]);
        g_a0[k] = __ldg(&w_init[k >> 4]) * __ldg(&x_init[k & 15]);
    }
}

// ---------------- K0b: gather mb rows, convert seq f32 -> fp16 ----------------
__global__ void __launch_bounds__(256) k0b_conv(const float* __restrict__ seq,
                                                const int* __restrict__ lengths,
                                                const int* __restrict__ mb) {
    const int b = blockIdx.x, seg = blockIdx.y;   // seg: 128 t-rows
    const int row = __ldg(&mb[b]);
    const int len = __ldg(&lengths[row]);
    if (seg * 128 >= len) return;
    const float4* src = reinterpret_cast<const float4*>(
        seq + ((size_t)row * T_LEN + seg * 128) * D_TONES);
    uint2* dst = reinterpret_cast<uint2*>(
        g_seqh + ((size_t)b * T_LEN + seg * 128) * D_TONES);
    for (int i = threadIdx.x; i < 128 * 22; i += 256) {
        float4 v = __ldg(&src[i]);
        dst[i] = make_uint2(h2u(__floats2half2_rn(v.x, v.y)),
                            h2u(__floats2half2_rn(v.z, v.w)));
    }
}

// ---------------- K1f: emission GEMM + rowmax + exp + parity-permuted E ----------------
__global__ void __launch_bounds__(256) k1f_emis(const int* __restrict__ lengths,
                                                const int* __restrict__ mb) {
    extern __shared__ __align__(16) unsigned char sraw[];
    __half (*Bsm)[DPAD] = reinterpret_cast<__half(*)[DPAD]>(sraw + SM_B);
    float* csm = reinterpret_cast<float*>(sraw + SM_CST);
    float (*rmx)[2][16] = reinterpret_cast<float(*)[2][16]>(sraw + SM_RMX);
    float* wsum = reinterpret_cast<float*>(sraw + SM_WSUM);
    unsigned* stg = reinterpret_cast<unsigned*>(sraw + SM_STG);   // [32][132] words

    const int b = blockIdx.x, chunk = blockIdx.y;   // chunk: 2 tiles each
    const int tid = threadIdx.x;
    const int len = __ldg(&lengths[__ldg(&mb[b])]);
    const int tstart = chunk * 2, tend = tstart + 2;
    if (tstart * TILE_T >= len) {
        if (tid == 0) g_msum4[b * 4 + chunk] = 0.0f;
        return;
    }

    const unsigned aBufBase = smem_u32(sraw + SM_A);
    const __half* seqb = g_seqh + (size_t)b * T_LEN * D_TONES;

    // prologue: prefetch A(tstart) into buf0
    {
        const char* src = reinterpret_cast<const char*>(seqb + (size_t)tstart * TILE_T * D_TONES);
        for (int cidx = tid; cidx < 704; cidx += 256) {
            int r = cidx / 11, o = cidx % 11;
            CP_ASYNC16(aBufBase + r * 208 + o * 16, src + r * 176 + o * 16);
        }
        CP_COMMIT();
    }
    // load B + cst; zero A pad cols (88..103) of both buffers
    {
        const uint4* wp = reinterpret_cast<const uint4*>(g_wdh);
        uint4* bq = reinterpret_cast<uint4*>(&Bsm[0][0]);
        for (int idx = tid; idx < 256 * 13; idx += 256) bq[idx] = __ldg(&wp[idx]);
        csm[tid] = g_cst[tid];
        for (int r = tid; r < 2 * TILE_T; r += 256) {
            char* base = reinterpret_cast<char*>(sraw) + SM_A + (r >> 6) * 13312 + (r & 63) * 208;
            *reinterpret_cast<uint4*>(base + 176) = make_uint4(0, 0, 0, 0);
            *reinterpret_cast<uint4*>(base + 192) = make_uint4(0, 0, 0, 0);
        }
    }

    const int w = tid >> 5, lane = tid & 31;
    const int rg = w & 3;           // row group (16 rows)
    const int g  = w >> 2;          // col group
    const int l4 = lane & 3, lr = lane >> 2;
    const unsigned aOff = (rg * 16 + (lane & 15)) * 208 + ((lane >> 4) * 8) * 2;
    const unsigned bBase = smem_u32(&Bsm[g * 64 + ((lane >> 4) * 8) + (lane & 7)][((lane >> 3) & 1) * 8]);

    float msl = 0.0f;
    int buf = 0;

    for (int tile = tstart; tile < tend; tile++) {
        const int t0 = tile * TILE_T;
        if (t0 >= len) break;

        // prefetch next tile's A into the other buffer
        if (tile + 1 < tend && (tile + 1) * TILE_T < len) {
            const char* src = reinterpret_cast<const char*>(
                seqb + (size_t)(tile + 1) * TILE_T * D_TONES);
            const unsigned dstb = aBufBase + (buf ^ 1) * 13312;
            for (int cidx = tid; cidx < 704; cidx += 256) {
                int r = cidx / 11, o = cidx % 11;
                CP_ASYNC16(dstb + r * 208 + o * 16, src + r * 176 + o * 16);
            }
        }
        CP_COMMIT();
        CP_WAIT1();
        __syncthreads();   // [S1] current A visible to all

        const unsigned aBase = aBufBase + buf * 13312 + aOff;

        float c[2][8][4];
#pragma unroll
        for (int cg = 0; cg < 2; cg++)
#pragma unroll
            for (int q = 0; q < 8; q++) {
                c[cg][q][0] = 0.0f; c[cg][q][1] = 0.0f;
                c[cg][q][2] = 0.0f; c[cg][q][3] = 0.0f;
            }

#pragma unroll
        for (int ks = 0; ks < 6; ks++) {
            unsigned a0, a1, a2, a3;
            asm volatile("ldmatrix.sync.aligned.m8n8.x4.shared.b16 {%0,%1,%2,%3},[%4];"
                         : "=r"(a0), "=r"(a1), "=r"(a2), "=r"(a3) : "r"(aBase + ks * 32));
#pragma unroll
            for (int cg = 0; cg < 2; cg++) {
#pragma unroll
                for (int q16 = 0; q16 < 4; q16++) {
                    unsigned b0, b1, b2, b3;
                    asm volatile("ldmatrix.sync.aligned.m8n8.x4.shared.b16 {%0,%1,%2,%3},[%4];"
                                 : "=r"(b0), "=r"(b1), "=r"(b2), "=r"(b3)
                                 : "r"(bBase + (cg * 128 + q16 * 16) * (DPAD * 2) + ks * 32));
                    float* cl0 = c[cg][q16 * 2];
                    float* cl1 = c[cg][q16 * 2 + 1];
                    asm volatile("mma.sync.aligned.m16n8k16.row.col.f32.f16.f16.f32 "
                                 "{%0,%1,%2,%3},{%4,%5,%6,%7},{%8,%9},{%0,%1,%2,%3};"
                                 : "+f"(cl0[0]), "+f"(cl0[1]), "+f"(cl0[2]), "+f"(cl0[3])
                                 : "r"(a0), "r"(a1), "r"(a2), "r"(a3), "r"(b0), "r"(b1));
                    asm volatile("mma.sync.aligned.m16n8k16.row.col.f32.f16.f16.f32 "
                                 "{%0,%1,%2,%3},{%4,%5,%6,%7},{%8,%9},{%0,%1,%2,%3};"
                                 : "+f"(cl1[0]), "+f"(cl1[1]), "+f"(cl1[2]), "+f"(cl1[3])
                                 : "r"(a0), "r"(a1), "r"(a2), "r"(a3), "r"(b2), "r"(b3));
                }
            }
        }

        // +cst, row max (quad + cross-warp via smem)
        float vmax0 = -3.4e38f, vmax1 = -3.4e38f;
#pragma unroll
        for (int cg = 0; cg < 2; cg++)
#pragma unroll
            for (int q = 0; q < 8; q++) {
                int col = g * 64 + cg * 128 + q * 8 + l4 * 2;
                float2 cst2 = *reinterpret_cast<const float2*>(&csm[col]);
                c[cg][q][0] += cst2.x; c[cg][q][1] += cst2.y;
                c[cg][q][2] += cst2.x; c[cg][q][3] += cst2.y;
                vmax0 = fmaxf(vmax0, fmaxf(c[cg][q][0], c[cg][q][1]));
                vmax1 = fmaxf(vmax1, fmaxf(c[cg][q][2], c[cg][q][3]));
            }
        vmax0 = fmaxf(vmax0, __shfl_xor_sync(0xffffffffu, vmax0, 1));
        vmax0 = fmaxf(vmax0, __shfl_xor_sync(0xffffffffu, vmax0, 2));
        vmax1 = fmaxf(vmax1, __shfl_xor_sync(0xffffffffu, vmax1, 1));
        vmax1 = fmaxf(vmax1, __shfl_xor_sync(0xffffffffu, vmax1, 2));
        if (l4 == 0) {
            rmx[rg][g][lr] = vmax0;
            rmx[rg][g][lr + 8] = vmax1;
        }
        __syncthreads();   // [S2]
        const float mx0 = fmaxf(rmx[rg][0][lr], rmx[rg][1][lr]);
        const float mx1 = fmaxf(rmx[rg][0][lr + 8], rmx[rg][1][lr + 8]);

        if (g == 0 && l4 == 0) {
            if (t0 + rg * 16 + lr < len) msl += mx0;
            if (t0 + rg * 16 + lr + 8 < len) msl += mx1;
        }

        // exp + pack
        unsigned ue[2][8][2];
#pragma unroll
        for (int cg = 0; cg < 2; cg++)
#pragma unroll
            for (int q = 0; q < 8; q++) {
                ue[cg][q][0] = packh2(__expf(c[cg][q][0] - mx0), __expf(c[cg][q][1] - mx0));
                ue[cg][q][1] = packh2(__expf(c[cg][q][2] - mx1), __expf(c[cg][q][3] - mx1));
            }

        const int r0 = (rg & 1) * 16 + lr;   // staging row (0..31)
#pragma unroll
        for (int phase = 0; phase < 2; phase++) {
            if ((rg >> 1) == phase) {
#pragma unroll
                for (int cg = 0; cg < 2; cg++)
#pragma unroll
                    for (int q = 0; q < 8; q++) {
                        int wv = g * 32 + cg * 64 + q * 4 + l4;
                        stg[r0 * 132 + SWZ(wv)] = ue[cg][q][0];
                        stg[(r0 + 8) * 132 + SWZ(wv)] = ue[cg][q][1];
                    }
            }
            __syncthreads();   // staging ready

            // copy-out: even absolute t -> normal fragment; odd -> transposed fragment.
            // staging row tl (0..31); absolute t = t0 + 32*phase + tl; parity = tl&1 = w&1.
            uint4* eo = reinterpret_cast<uint4*>(g_Ep) +
                        ((size_t)b * T_LEN + t0 + 32 * phase) * 32;
            if ((w & 1) == 0) {
                const int w0 = 8 * (lane >> 2) + (lane & 3);
                const int i0 = SWZ(w0), i1 = SWZ(w0 + 64), i2 = SWZ(w0 + 4), i3 = SWZ(w0 + 68);
#pragma unroll
                for (int i = 0; i < 4; i++) {
                    int tl = 8 * i + w;
                    int base = tl * 132;
                    uint4 o;
                    o.x = stg[base + i0];
                    o.y = stg[base + i1];
                    o.z = stg[base + i2];
                    o.w = stg[base + i3];
                    eo[tl * 32 + lane] = o;
                }
            } else {
                const unsigned short* hp = reinterpret_cast<const unsigned short*>(stg);
                const int g2 = lane >> 2, t42 = lane & 3;
                const int s00 = 32 * t42 + g2;       // a0 lo state
                const int s10 = s00 + 8;             // a1 lo state
                const int hsel = g2 & 1;
                const int j0a = SWZ(s00 >> 1) * 2 + hsel;
                const int j0b = SWZ((s00 + 16) >> 1) * 2 + hsel;
                const int j1a = SWZ(s10 >> 1) * 2 + hsel;
                const int j1b = SWZ((s10 + 16) >> 1) * 2 + hsel;
                const int j2a = SWZ((s00 + 128) >> 1) * 2 + hsel;
                const int j2b = SWZ((s00 + 144) >> 1) * 2 + hsel;
                const int j3a = SWZ((s10 + 128) >> 1) * 2 + hsel;
                const int j3b = SWZ((s10 + 144) >> 1) * 2 + hsel;
#pragma unroll
                for (int i = 0; i < 4; i++) {
                    int tl = 8 * i + w;
                    int rb = tl * 264;
                    uint4 o;
                    o.x = (unsigned)hp[rb + j0a] | ((unsigned)hp[rb + j0b] << 16);
                    o.y = (unsigned)hp[rb + j1a] | ((unsigned)hp[rb + j1b] << 16);
                    o.z = (unsigned)hp[rb + j2a] | ((unsigned)hp[rb + j2b] << 16);
                    o.w = (unsigned)hp[rb + j3a] | ((unsigned)hp[rb + j3b] << 16);
                    eo[tl * 32 + lane] = o;
                }
            }
            __syncthreads();   // staging consumed
        }
        buf ^= 1;
    }

    msl = warpSumf(msl);
    if (g == 0 && lane == 0) wsum[rg] = msl;
    __syncthreads();
    if (tid == 0)
        g_msum4[b * 4 + chunk] = (wsum[0] + wsum[1]) + (wsum[2] + wsum[3]);
}

// ---------------- K2: f16 tensor-core recursion, warp per b, depth-8 prefetch -----------
__global__ void __launch_bounds__(128) k2_fwd(const float* __restrict__ probs_w,
                                              const float* __restrict__ probs_x,
                                              const int* __restrict__ lengths,
                                              const int* __restrict__ mb) {
    const int wid = threadIdx.x >> 5, lane = threadIdx.x & 31;
    const int b = blockIdx.x * 4 + wid;
    const int len = __ldg(&lengths[__ldg(&mb[b])]);

    const int g = lane >> 2, t4 = lane & 3;
    unsigned Xf[4], Wf[4];
    Xf[0] = packh2(__ldg(&probs_x[(2 * t4) * 16 + g]),     __ldg(&probs_x[(2 * t4 + 1) * 16 + g]));
    Xf[1] = packh2(__ldg(&probs_x[(2 * t4 + 8) * 16 + g]), __ldg(&probs_x[(2 * t4 + 9) * 16 + g]));
    Xf[2] = packh2(__ldg(&probs_x[(2 * t4) * 16 + g + 8]),     __ldg(&probs_x[(2 * t4 + 1) * 16 + g + 8]));
    Xf[3] = packh2(__ldg(&probs_x[(2 * t4 + 8) * 16 + g + 8]), __ldg(&probs_x[(2 * t4 + 9) * 16 + g + 8]));
    Wf[0] = packh2(__ldg(&probs_w[(2 * t4) * 16 + g]),     __ldg(&probs_w[(2 * t4 + 1) * 16 + g]));
    Wf[1] = packh2(__ldg(&probs_w[(2 * t4 + 8) * 16 + g]), __ldg(&probs_w[(2 * t4 + 9) * 16 + g]));
    Wf[2] = packh2(__ldg(&probs_w[(2 * t4) * 16 + g + 8]),     __ldg(&probs_w[(2 * t4 + 1) * 16 + g + 8]));
    Wf[3] = packh2(__ldg(&probs_w[(2 * t4 + 8) * 16 + g + 8]), __ldg(&probs_w[(2 * t4 + 9) * 16 + g + 8]));

    const uint4* ep = reinterpret_cast<const uint4*>(g_Ep) + (size_t)b * T_LEN * 32 + lane;
    const int bn = 16 * g + 2 * t4;

    unsigned Z[4];
    float C;
    {
        uint4 e0 = ep[0];   // t=0: normal layout
        float2 a0p = *reinterpret_cast<const float2*>(g_a0 + bn);
        float2 a1p = *reinterpret_cast<const float2*>(g_a0 + bn + 128);
        float2 a2p = *reinterpret_cast<const float2*>(g_a0 + bn + 8);
        float2 a3p = *reinterpret_cast<const float2*>(g_a0 + bn + 136);
        float2 e0p = __half22float2(u2h(e0.x));
        float2 e1p = __half22float2(u2h(e0.y));
        float2 e2p = __half22float2(u2h(e0.z));
        float2 e3p = __half22float2(u2h(e0.w));
        float p0x = a0p.x * e0p.x, p0y = a0p.y * e0p.y;
        float p1x = a1p.x * e1p.x, p1y = a1p.y * e1p.y;
        float p2x = a2p.x * e2p.x, p2y = a2p.y * e2p.y;
        float p3x = a3p.x * e3p.x, p3y = a3p.y * e3p.y;
        float s0 = ((p0x + p0y) + (p1x + p1y)) + ((p2x + p2y) + (p3x + p3y));
        s0 = warpSumf(s0);
        float kap0 = __fdividef(1024.0f, s0);
        C = -__logf(kap0);
        Z[0] = packh2(p0x * kap0, p0y * kap0);
        Z[1] = packh2(p1x * kap0, p1y * kap0);
        Z[2] = packh2(p2x * kap0, p2y * kap0);
        Z[3] = packh2(p3x * kap0, p3y * kap0);
    }

    __half2 kap2 = __half2half2(__float2half_rn(1.0f));
    float lk = 0.0f;

    uint4 EA[8];
#pragma unroll
    for (int u = 0; u < 8; u++) EA[u] = ep[(size_t)min(1 + u, len - 1) * 32];

    int t = 1;
    for (; t + 7 < len; t += 8) {
#pragma unroll
        for (int j = 0; j < 8; j++) {
            // step index = t + j; t ≡ 1 (mod 8) so parity(t+j) = !(j&1)
            if ((j & 1) == 0) stepZ_h(Z, C, EA[j], Xf, Wf, kap2, lk);  // odd t: normal->T
            else              stepZ_h(Z, C, EA[j], Wf, Xf, kap2, lk);  // even t: T->normal
            EA[j] = ep[(size_t)min(t + 8 + j, len - 1) * 32];
        }
    }
    for (int j = 0; t < len; t++, j++) {
        if (t & 1) stepZ_h(Z, C, EA[j], Xf, Wf, kap2, lk);
        else       stepZ_h(Z, C, EA[j], Wf, Xf, kap2, lk);
    }

    // finalize (orientation-invariant total sum)
    float2 f0 = __half22float2(u2h(Z[0]));
    float2 f1 = __half22float2(u2h(Z[1]));
    float2 f2 = __half22float2(u2h(Z[2]));
    float2 f3 = __half22float2(u2h(Z[3]));
    float s = ((f0.x + f0.y) + (f1.x + f1.y)) + ((f2.x + f2.y) + (f3.x + f3.y));
    s = warpSumf(s);
    C += __logf(s);
    if (lane == 0) g_C[b] = C;
}

// ---------------- K4: final sum (loglik = C + msum chunks) ----------------
__global__ void k4_sum(float* __restrict__ out) {
    __shared__ float red[8];
    const int lane = threadIdx.x & 31;
    const int w0 = threadIdx.x >> 5;
    float acc = 0.0f;
    for (int b = threadIdx.x; b < BATCH; b += 256)
        acc += g_C[b] + (g_msum4[4 * b] + g_msum4[4 * b + 1]) +
               (g_msum4[4 * b + 2] + g_msum4[4 * b + 3]);
    acc = warpSumf(acc);
    if (lane == 0) red[w0] = acc;
    __syncthreads();
    if (threadIdx.x == 0) {
        float s = red[0];
#pragma unroll
        for (int w = 1; w < 8; w++) s += red[w];
        out[0] = s;
    }
}

// ---------------- launch ----------------
extern "C" void kernel_launch(void* const* d_in, const int* in_sizes, int n_in,
                              void* d_out, int out_size) {
    const float* seq     = (const float*)d_in[0];
    const float* probs_w = (const float*)d_in[1];
    const float* probs_x = (const float*)d_in[2];
    const float* w_init  = (const float*)d_in[3];
    const float* x_init  = (const float*)d_in[4];
    const float* probs_y = (const float*)d_in[5];
    const int*   lengths = (const int*)d_in[6];
    const int*   mb      = (const int*)d_in[7];
    float* out = (float*)d_out;

    cudaFuncSetAttribute(k1f_emis, cudaFuncAttributeMaxDynamicSharedMemorySize, SM_TOT);

    k0_setup<<<K2ST, 128>>>(probs_y, w_init, x_init);
    k0b_conv<<<dim3(BATCH, 4), 256>>>(seq, lengths, mb);
    k1f_emis<<<dim3(BATCH, 4), 256, SM_TOT>>>(lengths, mb);
    k2_fwd<<<BATCH / 4, 128>>>(probs_w, probs_x, lengths, mb);
    k4_sum<<<1, 256>>>(out);
}

// round 14
// speedup vs baseline: 1.0705x; 1.0705x over previous
#include <cuda_runtime.h>
#include <cuda_fp16.h>
#include <cstdint>
#include <cstddef>

#define D_TONES 88
#define DPAD    104
#define T_LEN   512
#define K2ST    256
#define BATCH   1024
#define TILE_T  64
#define NTILES  8

// ---------------- device scratch ----------------
__device__ __align__(16) __half g_wdh[K2ST * DPAD];   // fp16 weights [k][d] (pad zeroed)
__device__ float g_cst[K2ST];                         // sum_d log1mp
__device__ float g_a0[K2ST];                          // linear init w_init*x_init
__device__ __align__(16) __half g_seqh[(size_t)BATCH * T_LEN * D_TONES]; // fp16 gathered seq
// E in k2-fragment-permuted layout: [b][t][lane][uint4]
// even t: normal orientation fragment; odd t: transposed orientation fragment
__device__ __align__(16) unsigned g_Ep[(size_t)BATCH * T_LEN * 128];
__device__ float g_msum2[BATCH * 2];
__device__ float g_C[BATCH];

// smem layout offsets for k1f (bytes)
#define SM_B    0                        // 256 x 104 half = 53248
#define SM_A    53248                    // 2 x 64 x 104 half = 26624
#define SM_CST  79872                    // 256 f32 = 1024
#define SM_RMX  80896                    // 2 x 2 x 4 x 16 f32 = 2048
#define SM_WSUM 82944                    // 8 f32 = 32
#define SM_STG  82976                    // 32 rows x 132 words x 4B = 16896
#define SM_TOT  99872

#define SWZ(wd) ((wd) ^ (((wd) >> 3) & 4))

// ---------------- helpers ----------------
__device__ __forceinline__ unsigned smem_u32(const void* p) {
    return (unsigned)__cvta_generic_to_shared(p);
}
#define CP_ASYNC16(dst, src) \
    asm volatile("cp.async.cg.shared.global [%0], [%1], 16;" :: "r"(dst), "l"(src))
#define CP_COMMIT() asm volatile("cp.async.commit_group;")
#define CP_WAIT1()  asm volatile("cp.async.wait_group 1;")

__device__ __forceinline__ float warpSumf(float v) {
#pragma unroll
    for (int s = 16; s > 0; s >>= 1) v += __shfl_xor_sync(0xffffffffu, v, s);
    return v;
}
// warp sum via integer redux (fixed point, scale 32) — approximate kappa is fine,
// since the APPLIED kappa is exactly bookkept.
__device__ __forceinline__ float warpSumRedux(float v) {
    unsigned pi = __float2uint_rn(fmaxf(v, 0.0f) * 32.0f);
    unsigned si;
    asm volatile("redux.sync.add.u32 %0, %1, 0xffffffff;" : "=r"(si) : "r"(pi));
    return __uint2float_rn(si) * 0.03125f;
}
__device__ __forceinline__ unsigned packh2(float lo, float hi) {
    __half2 h = __floats2half2_rn(lo, hi);
    return *reinterpret_cast<unsigned*>(&h);
}
__device__ __forceinline__ __half2 u2h(unsigned u) { return *reinterpret_cast<__half2*>(&u); }
__device__ __forceinline__ unsigned h2u(__half2 h) { return *reinterpret_cast<unsigned*>(&h); }
__device__ __forceinline__ unsigned movmT(unsigned s) {
    unsigned d;
    asm("movmatrix.sync.aligned.m8n8.trans.b16 %0,%1;" : "=r"(d) : "r"(s));
    return d;
}
// f16-accum mma (k2 recursion): C fragment layout == A fragment layout
__device__ __forceinline__ void mma_h16(unsigned& d0, unsigned& d1, const unsigned a[4],
                                        unsigned b0, unsigned b1) {
    asm volatile("mma.sync.aligned.m16n8k16.row.col.f16.f16.f16.f16 "
                 "{%0,%1},{%2,%3,%4,%5},{%6,%7},{%8,%9};"
                 : "=r"(d0), "=r"(d1)
                 : "r"(a[0]), "r"(a[1]), "r"(a[2]), "r"(a[3]), "r"(b0), "r"(b1),
                   "r"(0u), "r"(0u));
}

// one recursion step (f16 carry, orientation alternation, kappa lagged ONE step):
//   U = Z*M ; Ut = movm(U) ; Z' = (Ut*N) ⊙ (E*kap2)
// LAG-1 ONLY: s_t = 1024*r_t is unconditionally stable. (Lag-2 is an undamped
// oscillator L_t = L_{t-1} - L_{t-2} + log r_t -> fp16 overflow -> NaN; R13 failure.)
__device__ __forceinline__ void stepZ_h(unsigned Z[4], float& C, const uint4 E,
                                        const unsigned M[4], const unsigned N[4],
                                        __half2& kap2, float& lk) {
    __half2 hs = __hadd2(__hadd2(u2h(Z[0]), u2h(Z[1])), __hadd2(u2h(Z[2]), u2h(Z[3])));
    float2 fs = __half22float2(hs);
    float s = warpSumRedux(fs.x + fs.y);

    __half2 ek0 = __hmul2(u2h(E.x), kap2);
    __half2 ek1 = __hmul2(u2h(E.y), kap2);
    __half2 ek2 = __hmul2(u2h(E.z), kap2);
    __half2 ek3 = __hmul2(u2h(E.w), kap2);
    C -= lk;

    unsigned ul0, ul1, uh0, uh1;
    mma_h16(ul0, ul1, Z, M[0], M[1]);
    mma_h16(uh0, uh1, Z, M[2], M[3]);
    unsigned Ut[4];
    Ut[0] = movmT(ul0);
    Ut[1] = movmT(uh0);
    Ut[2] = movmT(ul1);
    Ut[3] = movmT(uh1);
    unsigned zl0, zl1, zh0, zh1;
    mma_h16(zl0, zl1, Ut, N[0], N[1]);
    mma_h16(zh0, zh1, Ut, N[2], N[3]);
    Z[0] = h2u(__hmul2(u2h(zl0), ek0));
    Z[1] = h2u(__hmul2(u2h(zl1), ek1));
    Z[2] = h2u(__hmul2(u2h(zh0), ek2));
    Z[3] = h2u(__hmul2(u2h(zh1), ek3));

    float kap = fminf(__fdividef(1024.0f, fmaxf(s, 1e-30f)), 60000.0f);
    __half kh = __float2half_rn(kap);
    kap2 = __half2half2(kh);
    lk = __logf(__half2float(kh));
}

// ---------------- K0: precompute (parallel: block per state k) ----------------
__global__ void __launch_bounds__(128) k0_setup(const float* __restrict__ probs_y,
                                                const float* __restrict__ w_init,
                                                const float* __restrict__ x_init) {
    __shared__ float red[4];
    const int k = blockIdx.x;
    const int d = threadIdx.x;
    float cs = 0.0f;
    if (d < D_TONES) {
        float py = __ldg(&probs_y[k * D_TONES + d]);
        float l1 = log1pf(-py);
        g_wdh[k * DPAD + d] = __float2half_rn(logf(py) - l1);
        cs = l1;
    } else if (d < DPAD) {
        g_wdh[k * DPAD + d] = __float2half_rn(0.0f);
    }
    cs = warpSumf(cs);
    if ((threadIdx.x & 31) == 0) red[threadIdx.x >> 5] = cs;
    __syncthreads();
    if (threadIdx.x == 0) {
        g_cst[k] = (red[0] + red[1]) + (red[2] + red[3]);
        g_a0[k] = __ldg(&w_init[k >> 4]) * __ldg(&x_init[k & 15]);
    }
}

// ---------------- K0b: gather mb rows, convert seq f32 -> fp16 ----------------
__global__ void __launch_bounds__(256) k0b_conv(const float* __restrict__ seq,
                                                const int* __restrict__ lengths,
                                                const int* __restrict__ mb) {
    const int b = blockIdx.x, seg = blockIdx.y;   // seg: 128 t-rows
    const int row = __ldg(&mb[b]);
    const int len = __ldg(&lengths[row]);
    if (seg * 128 >= len) return;
    const float4* src = reinterpret_cast<const float4*>(
        seq + ((size_t)row * T_LEN + seg * 128) * D_TONES);
    uint2* dst = reinterpret_cast<uint2*>(
        g_seqh + ((size_t)b * T_LEN + seg * 128) * D_TONES);
    for (int i = threadIdx.x; i < 128 * 22; i += 256) {
        float4 v = __ldg(&src[i]);
        dst[i] = make_uint2(h2u(__floats2half2_rn(v.x, v.y)),
                            h2u(__floats2half2_rn(v.z, v.w)));
    }
}

// ---------------- K1f: emission GEMM + rowmax + exp + parity-permuted E ----------------
// Warp map: rg = w&1 (32-row group, 2 A-fragments), g = w>>1 (64-col group).
// Each B fragment feeds 2 row-fragments -> B ldsm traffic halved vs 4rg x 2g.
__global__ void __launch_bounds__(256) k1f_emis(const int* __restrict__ lengths,
                                                const int* __restrict__ mb) {
    extern __shared__ __align__(16) unsigned char sraw[];
    __half (*Bsm)[DPAD] = reinterpret_cast<__half(*)[DPAD]>(sraw + SM_B);
    float* csm = reinterpret_cast<float*>(sraw + SM_CST);
    float (*rmx)[2][4][16] = reinterpret_cast<float(*)[2][4][16]>(sraw + SM_RMX);
    float* wsum = reinterpret_cast<float*>(sraw + SM_WSUM);
    unsigned* stg = reinterpret_cast<unsigned*>(sraw + SM_STG);   // [32][132] words

    const int b = blockIdx.x, halfb = blockIdx.y;   // halfb: tiles 0-3 / 4-7
    const int tid = threadIdx.x;
    const int len = __ldg(&lengths[__ldg(&mb[b])]);
    const int tstart = halfb * 4, tend = tstart + 4;
    if (tstart * TILE_T >= len) {
        if (tid == 0) g_msum2[b * 2 + halfb] = 0.0f;
        return;
    }

    const unsigned aBufBase = smem_u32(sraw + SM_A);
    const __half* seqb = g_seqh + (size_t)b * T_LEN * D_TONES;

    // prologue: prefetch A(tstart) into buf0
    {
        const char* src = reinterpret_cast<const char*>(seqb + (size_t)tstart * TILE_T * D_TONES);
        for (int cidx = tid; cidx < 704; cidx += 256) {
            int r = cidx / 11, o = cidx % 11;
            CP_ASYNC16(aBufBase + r * 208 + o * 16, src + r * 176 + o * 16);
        }
        CP_COMMIT();
    }
    // load B + cst; zero A pad cols (88..103) of both buffers
    {
        const uint4* wp = reinterpret_cast<const uint4*>(g_wdh);
        uint4* bq = reinterpret_cast<uint4*>(&Bsm[0][0]);
        for (int idx = tid; idx < 256 * 13; idx += 256) bq[idx] = __ldg(&wp[idx]);
        csm[tid] = g_cst[tid];
        for (int r = tid; r < 2 * TILE_T; r += 256) {
            char* base = reinterpret_cast<char*>(sraw) + SM_A + (r >> 6) * 13312 + (r & 63) * 208;
            *reinterpret_cast<uint4*>(base + 176) = make_uint4(0, 0, 0, 0);
            *reinterpret_cast<uint4*>(base + 192) = make_uint4(0, 0, 0, 0);
        }
    }

    const int w = tid >> 5, lane = tid & 31;
    const int rg = w & 1;           // 32-row group
    const int g  = w >> 1;          // 64-col group (0..3)
    const int l4 = lane & 3, lr = lane >> 2;
    const unsigned aOff0 = (rg * 32 + (lane & 15)) * 208 + ((lane >> 4) * 8) * 2;
    const unsigned aOff1 = aOff0 + 16 * 208;
    const unsigned bBase = smem_u32(&Bsm[g * 64 + ((lane >> 4) * 8) + (lane & 7)][((lane >> 3) & 1) * 8]);

    float msl = 0.0f;
    int buf = 0;

    for (int tile = tstart; tile < tend; tile++) {
        const int t0 = tile * TILE_T;
        if (t0 >= len) break;

        // prefetch next tile's A into the other buffer
        if (tile + 1 < tend && (tile + 1) * TILE_T < len) {
            const char* src = reinterpret_cast<const char*>(
                seqb + (size_t)(tile + 1) * TILE_T * D_TONES);
            const unsigned dstb = aBufBase + (buf ^ 1) * 13312;
            for (int cidx = tid; cidx < 704; cidx += 256) {
                int r = cidx / 11, o = cidx % 11;
                CP_ASYNC16(dstb + r * 208 + o * 16, src + r * 176 + o * 16);
            }
        }
        CP_COMMIT();
        CP_WAIT1();
        __syncthreads();   // [S1] current A visible

        const unsigned aBase0 = aBufBase + buf * 13312 + aOff0;
        const unsigned aBase1 = aBufBase + buf * 13312 + aOff1;

        float c[2][8][4];   // [row-frag][q(8 cols of 8)][quad]
#pragma unroll
        for (int f = 0; f < 2; f++)
#pragma unroll
            for (int q = 0; q < 8; q++) {
                c[f][q][0] = 0.0f; c[f][q][1] = 0.0f;
                c[f][q][2] = 0.0f; c[f][q][3] = 0.0f;
            }

#pragma unroll
        for (int ks = 0; ks < 6; ks++) {
            unsigned a00, a01, a02, a03, a10, a11, a12, a13;
            asm volatile("ldmatrix.sync.aligned.m8n8.x4.shared.b16 {%0,%1,%2,%3},[%4];"
                         : "=r"(a00), "=r"(a01), "=r"(a02), "=r"(a03) : "r"(aBase0 + ks * 32));
            asm volatile("ldmatrix.sync.aligned.m8n8.x4.shared.b16 {%0,%1,%2,%3},[%4];"
                         : "=r"(a10), "=r"(a11), "=r"(a12), "=r"(a13) : "r"(aBase1 + ks * 32));
#pragma unroll
            for (int q16 = 0; q16 < 4; q16++) {
                unsigned b0, b1, b2, b3;
                asm volatile("ldmatrix.sync.aligned.m8n8.x4.shared.b16 {%0,%1,%2,%3},[%4];"
                             : "=r"(b0), "=r"(b1), "=r"(b2), "=r"(b3)
                             : "r"(bBase + q16 * 16 * (DPAD * 2) + ks * 32));
                float* c00 = c[0][q16 * 2];
                float* c01 = c[0][q16 * 2 + 1];
                float* c10 = c[1][q16 * 2];
                float* c11 = c[1][q16 * 2 + 1];
                asm volatile("mma.sync.aligned.m16n8k16.row.col.f32.f16.f16.f32 "
                             "{%0,%1,%2,%3},{%4,%5,%6,%7},{%8,%9},{%0,%1,%2,%3};"
                             : "+f"(c00[0]), "+f"(c00[1]), "+f"(c00[2]), "+f"(c00[3])
                             : "r"(a00), "r"(a01), "r"(a02), "r"(a03), "r"(b0), "r"(b1));
                asm volatile("mma.sync.aligned.m16n8k16.row.col.f32.f16.f16.f32 "
                             "{%0,%1,%2,%3},{%4,%5,%6,%7},{%8,%9},{%0,%1,%2,%3};"
                             : "+f"(c01[0]), "+f"(c01[1]), "+f"(c01[2]), "+f"(c01[3])
                             : "r"(a00), "r"(a01), "r"(a02), "r"(a03), "r"(b2), "r"(b3));
                asm volatile("mma.sync.aligned.m16n8k16.row.col.f32.f16.f16.f32 "
                             "{%0,%1,%2,%3},{%4,%5,%6,%7},{%8,%9},{%0,%1,%2,%3};"
                             : "+f"(c10[0]), "+f"(c10[1]), "+f"(c10[2]), "+f"(c10[3])
                             : "r"(a10), "r"(a11), "r"(a12), "r"(a13), "r"(b0), "r"(b1));
                asm volatile("mma.sync.aligned.m16n8k16.row.col.f32.f16.f16.f32 "
                             "{%0,%1,%2,%3},{%4,%5,%6,%7},{%8,%9},{%0,%1,%2,%3};"
                             : "+f"(c11[0]), "+f"(c11[1]), "+f"(c11[2]), "+f"(c11[3])
                             : "r"(a10), "r"(a11), "r"(a12), "r"(a13), "r"(b2), "r"(b3));
            }
        }

        // +cst, row max (quad + cross-warp over 4 col groups via smem)
        float vm[2][2];
        vm[0][0] = vm[0][1] = vm[1][0] = vm[1][1] = -3.4e38f;
#pragma unroll
        for (int f = 0; f < 2; f++)
#pragma unroll
            for (int q = 0; q < 8; q++) {
                int col = g * 64 + q * 8 + l4 * 2;
                float2 cst2 = *reinterpret_cast<const float2*>(&csm[col]);
                c[f][q][0] += cst2.x; c[f][q][1] += cst2.y;
                c[f][q][2] += cst2.x; c[f][q][3] += cst2.y;
                vm[f][0] = fmaxf(vm[f][0], fmaxf(c[f][q][0], c[f][q][1]));
                vm[f][1] = fmaxf(vm[f][1], fmaxf(c[f][q][2], c[f][q][3]));
            }
#pragma unroll
        for (int f = 0; f < 2; f++) {
            vm[f][0] = fmaxf(vm[f][0], __shfl_xor_sync(0xffffffffu, vm[f][0], 1));
            vm[f][0] = fmaxf(vm[f][0], __shfl_xor_sync(0xffffffffu, vm[f][0], 2));
            vm[f][1] = fmaxf(vm[f][1], __shfl_xor_sync(0xffffffffu, vm[f][1], 1));
            vm[f][1] = fmaxf(vm[f][1], __shfl_xor_sync(0xffffffffu, vm[f][1], 2));
        }
        if (l4 == 0) {
            rmx[rg][0][g][lr] = vm[0][0];
            rmx[rg][0][g][lr + 8] = vm[0][1];
            rmx[rg][1][g][lr] = vm[1][0];
            rmx[rg][1][g][lr + 8] = vm[1][1];
        }
        __syncthreads();   // [S2]
        float mx[2][2];
#pragma unroll
        for (int f = 0; f < 2; f++) {
            mx[f][0] = fmaxf(fmaxf(rmx[rg][f][0][lr], rmx[rg][f][1][lr]),
                             fmaxf(rmx[rg][f][2][lr], rmx[rg][f][3][lr]));
            mx[f][1] = fmaxf(fmaxf(rmx[rg][f][0][lr + 8], rmx[rg][f][1][lr + 8]),
                             fmaxf(rmx[rg][f][2][lr + 8], rmx[rg][f][3][lr + 8]));
        }

        if (g == 0 && l4 == 0) {
            int rbase = t0 + rg * 32;
            if (rbase + lr < len) msl += mx[0][0];
            if (rbase + lr + 8 < len) msl += mx[0][1];
            if (rbase + 16 + lr < len) msl += mx[1][0];
            if (rbase + 16 + lr + 8 < len) msl += mx[1][1];
        }

        // exp + pack
        unsigned ue[2][8][2];
#pragma unroll
        for (int f = 0; f < 2; f++)
#pragma unroll
            for (int q = 0; q < 8; q++) {
                ue[f][q][0] = packh2(__expf(c[f][q][0] - mx[f][0]), __expf(c[f][q][1] - mx[f][0]));
                ue[f][q][1] = packh2(__expf(c[f][q][2] - mx[f][1]), __expf(c[f][q][3] - mx[f][1]));
            }

#pragma unroll
        for (int phase = 0; phase < 2; phase++) {
            if (rg == phase) {
#pragma unroll
                for (int f = 0; f < 2; f++) {
                    int r0f = f * 16 + lr;
#pragma unroll
                    for (int q = 0; q < 8; q++) {
                        int wv = g * 32 + q * 4 + l4;
                        stg[r0f * 132 + SWZ(wv)] = ue[f][q][0];
                        stg[(r0f + 8) * 132 + SWZ(wv)] = ue[f][q][1];
                    }
                }
            }
            __syncthreads();   // staging ready

            // copy-out: even absolute t -> normal fragment; odd -> transposed fragment.
            uint4* eo = reinterpret_cast<uint4*>(g_Ep) +
                        ((size_t)b * T_LEN + t0 + 32 * phase) * 32;
            if ((w & 1) == 0) {
                const int w0 = 8 * (lane >> 2) + (lane & 3);
                const int i0 = SWZ(w0), i1 = SWZ(w0 + 64), i2 = SWZ(w0 + 4), i3 = SWZ(w0 + 68);
#pragma unroll
                for (int i = 0; i < 4; i++) {
                    int tl = 8 * i + w;
                    int base = tl * 132;
                    uint4 o;
                    o.x = stg[base + i0];
                    o.y = stg[base + i1];
                    o.z = stg[base + i2];
                    o.w = stg[base + i3];
                    eo[tl * 32 + lane] = o;
                }
            } else {
                const unsigned short* hp = reinterpret_cast<const unsigned short*>(stg);
                const int g2 = lane >> 2, t42 = lane & 3;
                const int s00 = 32 * t42 + g2;
                const int s10 = s00 + 8;
                const int hsel = g2 & 1;
                const int j0a = SWZ(s00 >> 1) * 2 + hsel;
                const int j0b = SWZ((s00 + 16) >> 1) * 2 + hsel;
                const int j1a = SWZ(s10 >> 1) * 2 + hsel;
                const int j1b = SWZ((s10 + 16) >> 1) * 2 + hsel;
                const int j2a = SWZ((s00 + 128) >> 1) * 2 + hsel;
                const int j2b = SWZ((s00 + 144) >> 1) * 2 + hsel;
                const int j3a = SWZ((s10 + 128) >> 1) * 2 + hsel;
                const int j3b = SWZ((s10 + 144) >> 1) * 2 + hsel;
#pragma unroll
                for (int i = 0; i < 4; i++) {
                    int tl = 8 * i + w;
                    int rb = tl * 264;
                    uint4 o;
                    o.x = (unsigned)hp[rb + j0a] | ((unsigned)hp[rb + j0b] << 16);
                    o.y = (unsigned)hp[rb + j1a] | ((unsigned)hp[rb + j1b] << 16);
                    o.z = (unsigned)hp[rb + j2a] | ((unsigned)hp[rb + j2b] << 16);
                    o.w = (unsigned)hp[rb + j3a] | ((unsigned)hp[rb + j3b] << 16);
                    eo[tl * 32 + lane] = o;
                }
            }
            __syncthreads();   // staging consumed
        }
        buf ^= 1;
    }

    msl = warpSumf(msl);
    if ((w >> 1) == 0 && lane == 0) wsum[w & 1] = msl;
    __syncthreads();
    if (tid == 0) g_msum2[b * 2 + halfb] = wsum[0] + wsum[1];
}

// ---------------- K2: f16 tensor-core recursion, warp per b, lag-1 kappa ----------------
__global__ void __launch_bounds__(128) k2_fwd(const float* __restrict__ probs_w,
                                              const float* __restrict__ probs_x,
                                              const int* __restrict__ lengths,
                                              const int* __restrict__ mb) {
    const int wid = threadIdx.x >> 5, lane = threadIdx.x & 31;
    const int b = blockIdx.x * 4 + wid;
    const int len = __ldg(&lengths[__ldg(&mb[b])]);

    const int g = lane >> 2, t4 = lane & 3;
    unsigned Xf[4], Wf[4];
    Xf[0] = packh2(__ldg(&probs_x[(2 * t4) * 16 + g]),     __ldg(&probs_x[(2 * t4 + 1) * 16 + g]));
    Xf[1] = packh2(__ldg(&probs_x[(2 * t4 + 8) * 16 + g]), __ldg(&probs_x[(2 * t4 + 9) * 16 + g]));
    Xf[2] = packh2(__ldg(&probs_x[(2 * t4) * 16 + g + 8]),     __ldg(&probs_x[(2 * t4 + 1) * 16 + g + 8]));
    Xf[3] = packh2(__ldg(&probs_x[(2 * t4 + 8) * 16 + g + 8]), __ldg(&probs_x[(2 * t4 + 9) * 16 + g + 8]));
    Wf[0] = packh2(__ldg(&probs_w[(2 * t4) * 16 + g]),     __ldg(&probs_w[(2 * t4 + 1) * 16 + g]));
    Wf[1] = packh2(__ldg(&probs_w[(2 * t4 + 8) * 16 + g]), __ldg(&probs_w[(2 * t4 + 9) * 16 + g]));
    Wf[2] = packh2(__ldg(&probs_w[(2 * t4) * 16 + g + 8]),     __ldg(&probs_w[(2 * t4 + 1) * 16 + g + 8]));
    Wf[3] = packh2(__ldg(&probs_w[(2 * t4 + 8) * 16 + g + 8]), __ldg(&probs_w[(2 * t4 + 9) * 16 + g + 8]));

    const uint4* ep = reinterpret_cast<const uint4*>(g_Ep) + (size_t)b * T_LEN * 32 + lane;
    const int bn = 16 * g + 2 * t4;

    unsigned Z[4];
    float C;
    {
        uint4 e0 = ep[0];   // t=0: normal layout
        float2 a0p = *reinterpret_cast<const float2*>(g_a0 + bn);
        float2 a1p = *reinterpret_cast<const float2*>(g_a0 + bn + 128);
        float2 a2p = *reinterpret_cast<const float2*>(g_a0 + bn + 8);
        float2 a3p = *reinterpret_cast<const float2*>(g_a0 + bn + 136);
        float2 e0p = __half22float2(u2h(e0.x));
        float2 e1p = __half22float2(u2h(e0.y));
        float2 e2p = __half22float2(u2h(e0.z));
        float2 e3p = __half22float2(u2h(e0.w));
        float p0x = a0p.x * e0p.x, p0y = a0p.y * e0p.y;
        float p1x = a1p.x * e1p.x, p1y = a1p.y * e1p.y;
        float p2x = a2p.x * e2p.x, p2y = a2p.y * e2p.y;
        float p3x = a3p.x * e3p.x, p3y = a3p.y * e3p.y;
        float s0 = ((p0x + p0y) + (p1x + p1y)) + ((p2x + p2y) + (p3x + p3y));
        s0 = warpSumf(s0);
        float kap0 = __fdividef(1024.0f, s0);
        C = -__logf(kap0);
        Z[0] = packh2(p0x * kap0, p0y * kap0);
        Z[1] = packh2(p1x * kap0, p1y * kap0);
        Z[2] = packh2(p2x * kap0, p2y * kap0);
        Z[3] = packh2(p3x * kap0, p3y * kap0);
    }

    __half2 kap2 = __half2half2(__float2half_rn(1.0f));
    float lk = 0.0f;

    uint4 EA[8];
#pragma unroll
    for (int u = 0; u < 8; u++) EA[u] = ep[(size_t)min(1 + u, len - 1) * 32];

    int t = 1;
    for (; t + 7 < len; t += 8) {
#pragma unroll
        for (int j = 0; j < 8; j++) {
            // step index = t + j; t ≡ 1 (mod 8) so (j&1)==0 -> odd t
            if ((j & 1) == 0) stepZ_h(Z, C, EA[j], Xf, Wf, kap2, lk);
            else              stepZ_h(Z, C, EA[j], Wf, Xf, kap2, lk);
            EA[j] = ep[(size_t)min(t + 8 + j, len - 1) * 32];
        }
    }
    for (int j = 0; t < len; t++, j++) {
        if (t & 1) stepZ_h(Z, C, EA[j], Xf, Wf, kap2, lk);
        else       stepZ_h(Z, C, EA[j], Wf, Xf, kap2, lk);
    }

    float2 f0 = __half22float2(u2h(Z[0]));
    float2 f1 = __half22float2(u2h(Z[1]));
    float2 f2 = __half22float2(u2h(Z[2]));
    float2 f3 = __half22float2(u2h(Z[3]));
    float s = ((f0.x + f0.y) + (f1.x + f1.y)) + ((f2.x + f2.y) + (f3.x + f3.y));
    s = warpSumf(s);
    C += __logf(s);
    if (lane == 0) g_C[b] = C;
}

// ---------------- K4: final sum ----------------
__global__ void k4_sum(float* __restrict__ out) {
    __shared__ float red[8];
    const int lane = threadIdx.x & 31;
    const int w0 = threadIdx.x >> 5;
    float acc = 0.0f;
    for (int b = threadIdx.x; b < BATCH; b += 256)
        acc += g_C[b] + g_msum2[2 * b] + g_msum2[2 * b + 1];
    acc = warpSumf(acc);
    if (lane == 0) red[w0] = acc;
    __syncthreads();
    if (threadIdx.x == 0) {
        float s = red[0];
#pragma unroll
        for (int w = 1; w < 8; w++) s += red[w];
        out[0] = s;
    }
}

// ---------------- launch ----------------
extern "C" void kernel_launch(void* const* d_in, const int* in_sizes, int n_in,
                              void* d_out, int out_size) {
    const float* seq     = (const float*)d_in[0];
    const float* probs_w = (const float*)d_in[1];
    const float* probs_x = (const float*)d_in[2];
    const float* w_init  = (const float*)d_in[3];
    const float* x_init  = (const float*)d_in[4];
    const float* probs_y = (const float*)d_in[5];
    const int*   lengths = (const int*)d_in[6];
    const int*   mb      = (const int*)d_in[7];
    float* out = (float*)d_out;

    cudaFuncSetAttribute(k1f_emis, cudaFuncAttributeMaxDynamicSharedMemorySize, SM_TOT);

    k0_setup<<<K2ST, 128>>>(probs_y, w_init, x_init);
    k0b_conv<<<dim3(BATCH, 4), 256>>>(seq, lengths, mb);
    k1f_emis<<<dim3(BATCH, 2), 256, SM_TOT>>>(lengths, mb);
    k2_fwd<<<BATCH / 4, 128>>>(probs_w, probs_x, lengths, mb);
    k4_sum<<<1, 256>>>(out);
}

// round 15
// speedup vs baseline: 1.0950x; 1.0229x over previous
#include <cuda_runtime.h>
#include <cuda_fp16.h>
#include <cstdint>
#include <cstddef>

#define D_TONES 88
#define DPAD    104
#define T_LEN   512
#define K2ST    256
#define BATCH   1024
#define TILE_T  64
#define NTILES  8

// ---------------- device scratch ----------------
__device__ __align__(16) __half g_wdh[K2ST * DPAD];   // fp16 weights [k][d] (pad zeroed)
__device__ float g_cst[K2ST];                         // sum_d log1mp
__device__ float g_a0[K2ST];                          // linear init w_init*x_init
__device__ __align__(16) __half g_seqh[(size_t)BATCH * T_LEN * D_TONES]; // fp16 gathered seq
// E in k2-fragment-permuted layout: [b][t][lane][uint4] — ALWAYS normal A-fragment
__device__ __align__(16) unsigned g_Ep[(size_t)BATCH * T_LEN * 128];
__device__ float g_msum2[BATCH * 2];
__device__ float g_C[BATCH];

// smem layout offsets for k1f (bytes)
#define SM_B    0                        // 256 x 104 half = 53248
#define SM_A    53248                    // 2 x 64 x 104 half = 26624
#define SM_CST  79872                    // 256 f32 = 1024
#define SM_RMX  80896                    // 2 x 2 x 4 x 16 f32 = 2048
#define SM_WSUM 82944                    // 8 f32 = 32
#define SM_STG  82976                    // 32 rows x 132 words x 4B = 16896
#define SM_TOT  99872

#define SWZ(wd) ((wd) ^ (((wd) >> 3) & 4))

// ---------------- helpers ----------------
__device__ __forceinline__ unsigned smem_u32(const void* p) {
    return (unsigned)__cvta_generic_to_shared(p);
}
#define CP_ASYNC16(dst, src) \
    asm volatile("cp.async.cg.shared.global [%0], [%1], 16;" :: "r"(dst), "l"(src))
#define CP_COMMIT() asm volatile("cp.async.commit_group;")
#define CP_WAIT1()  asm volatile("cp.async.wait_group 1;")

__device__ __forceinline__ float warpSumf(float v) {
#pragma unroll
    for (int s = 16; s > 0; s >>= 1) v += __shfl_xor_sync(0xffffffffu, v, s);
    return v;
}
// warp sum via integer redux (fixed point, scale 32) — approximate kappa is fine,
// since the APPLIED kappa is exactly bookkept.
__device__ __forceinline__ float warpSumRedux(float v) {
    unsigned pi = __float2uint_rn(fmaxf(v, 0.0f) * 32.0f);
    unsigned si;
    asm volatile("redux.sync.add.u32 %0, %1, 0xffffffff;" : "=r"(si) : "r"(pi));
    return __uint2float_rn(si) * 0.03125f;
}
__device__ __forceinline__ unsigned packh2(float lo, float hi) {
    __half2 h = __floats2half2_rn(lo, hi);
    return *reinterpret_cast<unsigned*>(&h);
}
__device__ __forceinline__ __half2 u2h(unsigned u) { return *reinterpret_cast<__half2*>(&u); }
__device__ __forceinline__ unsigned h2u(__half2 h) { return *reinterpret_cast<unsigned*>(&h); }
// f16-accum mma: C fragment layout == A fragment layout; feeding a C/A-layout
// matrix as the B operand multiplies by its TRANSPOSE (free transpose).
__device__ __forceinline__ void mma_h16(unsigned& d0, unsigned& d1, const unsigned a[4],
                                        unsigned b0, unsigned b1) {
    asm volatile("mma.sync.aligned.m16n8k16.row.col.f16.f16.f16.f16 "
                 "{%0,%1},{%2,%3,%4,%5},{%6,%7},{%8,%9};"
                 : "=r"(d0), "=r"(d1)
                 : "r"(a[0]), "r"(a[1]), "r"(a[2]), "r"(a[3]), "r"(b0), "r"(b1),
                   "r"(0u), "r"(0u));
}

// one recursion step (f16 carry, dual-B-operand scheme, kappa lagged ONE step):
//   D1 = XT_A * (Z as B)  = X^T Z^T = (Z X)^T      (2 mma)
//   Z' = WT_A * (D1 as B) = W^T (Z X)              (2 mma)
//   Z  = Z' ⊙ (E * kappa)
// Chain: mma -> mma -> hmul. No movmatrix, no packs; E always normal layout.
// LAG-1 kappa only (lag-2 is an undamped oscillator -> NaN; R13 failure).
__device__ __forceinline__ void stepZ_d(unsigned Z[4], float& C, const uint4 E,
                                        const unsigned XT[4], const unsigned WT[4],
                                        __half2& kap2, float& lk) {
    __half2 hs = __hadd2(__hadd2(u2h(Z[0]), u2h(Z[1])), __hadd2(u2h(Z[2]), u2h(Z[3])));
    float2 fs = __half22float2(hs);
    float s = warpSumRedux(fs.x + fs.y);

    __half2 ek0 = __hmul2(u2h(E.x), kap2);
    __half2 ek1 = __hmul2(u2h(E.y), kap2);
    __half2 ek2 = __hmul2(u2h(E.z), kap2);
    __half2 ek3 = __hmul2(u2h(E.w), kap2);
    C -= lk;

    unsigned p0, p1, q0, q1;
    mma_h16(p0, p1, XT, Z[0], Z[2]);   // D1 cols 0-7   (B = Z^T rows 0-7)
    mma_h16(q0, q1, XT, Z[1], Z[3]);   // D1 cols 8-15  (B = Z^T rows 8-15)
    unsigned z0, z1, z2, z3;
    mma_h16(z0, z1, WT, p0, q0);       // Z' cols 0-7   (B = D1^T rows 0-7)
    mma_h16(z2, z3, WT, p1, q1);       // Z' cols 8-15
    Z[0] = h2u(__hmul2(u2h(z0), ek0));
    Z[1] = h2u(__hmul2(u2h(z1), ek1));
    Z[2] = h2u(__hmul2(u2h(z2), ek2));
    Z[3] = h2u(__hmul2(u2h(z3), ek3));

    float kap = fminf(__fdividef(1024.0f, fmaxf(s, 1e-30f)), 60000.0f);
    __half kh = __float2half_rn(kap);
    kap2 = __half2half2(kh);
    lk = __logf(__half2float(kh));
}

// ---------------- K0: precompute (parallel: block per state k) ----------------
__global__ void __launch_bounds__(128) k0_setup(const float* __restrict__ probs_y,
                                                const float* __restrict__ w_init,
                                                const float* __restrict__ x_init) {
    __shared__ float red[4];
    const int k = blockIdx.x;
    const int d = threadIdx.x;
    float cs = 0.0f;
    if (d < D_TONES) {
        float py = __ldg(&probs_y[k * D_TONES + d]);
        float l1 = log1pf(-py);
        g_wdh[k * DPAD + d] = __float2half_rn(logf(py) - l1);
        cs = l1;
    } else if (d < DPAD) {
        g_wdh[k * DPAD + d] = __float2half_rn(0.0f);
    }
    cs = warpSumf(cs);
    if ((threadIdx.x & 31) == 0) red[threadIdx.x >> 5] = cs;
    __syncthreads();
    if (threadIdx.x == 0) {
        g_cst[k] = (red[0] + red[1]) + (red[2] + red[3]);
        g_a0[k] = __ldg(&w_init[k >> 4]) * __ldg(&x_init[k & 15]);
    }
}

// ---------------- K0b: gather mb rows, convert seq f32 -> fp16 ----------------
__global__ void __launch_bounds__(256) k0b_conv(const float* __restrict__ seq,
                                                const int* __restrict__ lengths,
                                                const int* __restrict__ mb) {
    const int b = blockIdx.x, seg = blockIdx.y;   // seg: 128 t-rows
    const int row = __ldg(&mb[b]);
    const int len = __ldg(&lengths[row]);
    if (seg * 128 >= len) return;
    const float4* src = reinterpret_cast<const float4*>(
        seq + ((size_t)row * T_LEN + seg * 128) * D_TONES);
    uint2* dst = reinterpret_cast<uint2*>(
        g_seqh + ((size_t)b * T_LEN + seg * 128) * D_TONES);
    for (int i = threadIdx.x; i < 128 * 22; i += 256) {
        float4 v = __ldg(&src[i]);
        dst[i] = make_uint2(h2u(__floats2half2_rn(v.x, v.y)),
                            h2u(__floats2half2_rn(v.z, v.w)));
    }
}

// ---------------- K1f: emission GEMM + rowmax + exp + permuted E (normal layout) --------
// Warp map: rg = w&1 (32-row group, 2 A-fragments), g = w>>1 (64-col group).
__global__ void __launch_bounds__(256) k1f_emis(const int* __restrict__ lengths,
                                                const int* __restrict__ mb) {
    extern __shared__ __align__(16) unsigned char sraw[];
    __half (*Bsm)[DPAD] = reinterpret_cast<__half(*)[DPAD]>(sraw + SM_B);
    float* csm = reinterpret_cast<float*>(sraw + SM_CST);
    float (*rmx)[2][4][16] = reinterpret_cast<float(*)[2][4][16]>(sraw + SM_RMX);
    float* wsum = reinterpret_cast<float*>(sraw + SM_WSUM);
    unsigned* stg = reinterpret_cast<unsigned*>(sraw + SM_STG);   // [32][132] words

    const int b = blockIdx.x, halfb = blockIdx.y;   // halfb: tiles 0-3 / 4-7
    const int tid = threadIdx.x;
    const int len = __ldg(&lengths[__ldg(&mb[b])]);
    const int tstart = halfb * 4, tend = tstart + 4;
    if (tstart * TILE_T >= len) {
        if (tid == 0) g_msum2[b * 2 + halfb] = 0.0f;
        return;
    }

    const unsigned aBufBase = smem_u32(sraw + SM_A);
    const __half* seqb = g_seqh + (size_t)b * T_LEN * D_TONES;

    // prologue: prefetch A(tstart) into buf0
    {
        const char* src = reinterpret_cast<const char*>(seqb + (size_t)tstart * TILE_T * D_TONES);
        for (int cidx = tid; cidx < 704; cidx += 256) {
            int r = cidx / 11, o = cidx % 11;
            CP_ASYNC16(aBufBase + r * 208 + o * 16, src + r * 176 + o * 16);
        }
        CP_COMMIT();
    }
    // load B + cst; zero A pad cols (88..103) of both buffers
    {
        const uint4* wp = reinterpret_cast<const uint4*>(g_wdh);
        uint4* bq = reinterpret_cast<uint4*>(&Bsm[0][0]);
        for (int idx = tid; idx < 256 * 13; idx += 256) bq[idx] = __ldg(&wp[idx]);
        csm[tid] = g_cst[tid];
        for (int r = tid; r < 2 * TILE_T; r += 256) {
            char* base = reinterpret_cast<char*>(sraw) + SM_A + (r >> 6) * 13312 + (r & 63) * 208;
            *reinterpret_cast<uint4*>(base + 176) = make_uint4(0, 0, 0, 0);
            *reinterpret_cast<uint4*>(base + 192) = make_uint4(0, 0, 0, 0);
        }
    }

    const int w = tid >> 5, lane = tid & 31;
    const int rg = w & 1;           // 32-row group
    const int g  = w >> 1;          // 64-col group (0..3)
    const int l4 = lane & 3, lr = lane >> 2;
    const unsigned aOff0 = (rg * 32 + (lane & 15)) * 208 + ((lane >> 4) * 8) * 2;
    const unsigned aOff1 = aOff0 + 16 * 208;
    const unsigned bBase = smem_u32(&Bsm[g * 64 + ((lane >> 4) * 8) + (lane & 7)][((lane >> 3) & 1) * 8]);

    float msl = 0.0f;
    int buf = 0;

    for (int tile = tstart; tile < tend; tile++) {
        const int t0 = tile * TILE_T;
        if (t0 >= len) break;

        // prefetch next tile's A into the other buffer
        if (tile + 1 < tend && (tile + 1) * TILE_T < len) {
            const char* src = reinterpret_cast<const char*>(
                seqb + (size_t)(tile + 1) * TILE_T * D_TONES);
            const unsigned dstb = aBufBase + (buf ^ 1) * 13312;
            for (int cidx = tid; cidx < 704; cidx += 256) {
                int r = cidx / 11, o = cidx % 11;
                CP_ASYNC16(dstb + r * 208 + o * 16, src + r * 176 + o * 16);
            }
        }
        CP_COMMIT();
        CP_WAIT1();
        __syncthreads();   // [S1] current A visible

        const unsigned aBase0 = aBufBase + buf * 13312 + aOff0;
        const unsigned aBase1 = aBufBase + buf * 13312 + aOff1;

        float c[2][8][4];   // [row-frag][q(8 cols of 8)][quad]
#pragma unroll
        for (int f = 0; f < 2; f++)
#pragma unroll
            for (int q = 0; q < 8; q++) {
                c[f][q][0] = 0.0f; c[f][q][1] = 0.0f;
                c[f][q][2] = 0.0f; c[f][q][3] = 0.0f;
            }

#pragma unroll
        for (int ks = 0; ks < 6; ks++) {
            unsigned a00, a01, a02, a03, a10, a11, a12, a13;
            asm volatile("ldmatrix.sync.aligned.m8n8.x4.shared.b16 {%0,%1,%2,%3},[%4];"
                         : "=r"(a00), "=r"(a01), "=r"(a02), "=r"(a03) : "r"(aBase0 + ks * 32));
            asm volatile("ldmatrix.sync.aligned.m8n8.x4.shared.b16 {%0,%1,%2,%3},[%4];"
                         : "=r"(a10), "=r"(a11), "=r"(a12), "=r"(a13) : "r"(aBase1 + ks * 32));
#pragma unroll
            for (int q16 = 0; q16 < 4; q16++) {
                unsigned b0, b1, b2, b3;
                asm volatile("ldmatrix.sync.aligned.m8n8.x4.shared.b16 {%0,%1,%2,%3},[%4];"
                             : "=r"(b0), "=r"(b1), "=r"(b2), "=r"(b3)
                             : "r"(bBase + q16 * 16 * (DPAD * 2) + ks * 32));
                float* c00 = c[0][q16 * 2];
                float* c01 = c[0][q16 * 2 + 1];
                float* c10 = c[1][q16 * 2];
                float* c11 = c[1][q16 * 2 + 1];
                asm volatile("mma.sync.aligned.m16n8k16.row.col.f32.f16.f16.f32 "
                             "{%0,%1,%2,%3},{%4,%5,%6,%7},{%8,%9},{%0,%1,%2,%3};"
                             : "+f"(c00[0]), "+f"(c00[1]), "+f"(c00[2]), "+f"(c00[3])
                             : "r"(a00), "r"(a01), "r"(a02), "r"(a03), "r"(b0), "r"(b1));
                asm volatile("mma.sync.aligned.m16n8k16.row.col.f32.f16.f16.f32 "
                             "{%0,%1,%2,%3},{%4,%5,%6,%7},{%8,%9},{%0,%1,%2,%3};"
                             : "+f"(c01[0]), "+f"(c01[1]), "+f"(c01[2]), "+f"(c01[3])
                             : "r"(a00), "r"(a01), "r"(a02), "r"(a03), "r"(b2), "r"(b3));
                asm volatile("mma.sync.aligned.m16n8k16.row.col.f32.f16.f16.f32 "
                             "{%0,%1,%2,%3},{%4,%5,%6,%7},{%8,%9},{%0,%1,%2,%3};"
                             : "+f"(c10[0]), "+f"(c10[1]), "+f"(c10[2]), "+f"(c10[3])
                             : "r"(a10), "r"(a11), "r"(a12), "r"(a13), "r"(b0), "r"(b1));
                asm volatile("mma.sync.aligned.m16n8k16.row.col.f32.f16.f16.f32 "
                             "{%0,%1,%2,%3},{%4,%5,%6,%7},{%8,%9},{%0,%1,%2,%3};"
                             : "+f"(c11[0]), "+f"(c11[1]), "+f"(c11[2]), "+f"(c11[3])
                             : "r"(a10), "r"(a11), "r"(a12), "r"(a13), "r"(b2), "r"(b3));
            }
        }

        // +cst, row max (quad + cross-warp over 4 col groups via smem)
        float vm[2][2];
        vm[0][0] = vm[0][1] = vm[1][0] = vm[1][1] = -3.4e38f;
#pragma unroll
        for (int f = 0; f < 2; f++)
#pragma unroll
            for (int q = 0; q < 8; q++) {
                int col = g * 64 + q * 8 + l4 * 2;
                float2 cst2 = *reinterpret_cast<const float2*>(&csm[col]);
                c[f][q][0] += cst2.x; c[f][q][1] += cst2.y;
                c[f][q][2] += cst2.x; c[f][q][3] += cst2.y;
                vm[f][0] = fmaxf(vm[f][0], fmaxf(c[f][q][0], c[f][q][1]));
                vm[f][1] = fmaxf(vm[f][1], fmaxf(c[f][q][2], c[f][q][3]));
            }
#pragma unroll
        for (int f = 0; f < 2; f++) {
            vm[f][0] = fmaxf(vm[f][0], __shfl_xor_sync(0xffffffffu, vm[f][0], 1));
            vm[f][0] = fmaxf(vm[f][0], __shfl_xor_sync(0xffffffffu, vm[f][0], 2));
            vm[f][1] = fmaxf(vm[f][1], __shfl_xor_sync(0xffffffffu, vm[f][1], 1));
            vm[f][1] = fmaxf(vm[f][1], __shfl_xor_sync(0xffffffffu, vm[f][1], 2));
        }
        if (l4 == 0) {
            rmx[rg][0][g][lr] = vm[0][0];
            rmx[rg][0][g][lr + 8] = vm[0][1];
            rmx[rg][1][g][lr] = vm[1][0];
            rmx[rg][1][g][lr + 8] = vm[1][1];
        }
        __syncthreads();   // [S2]
        float mx[2][2];
#pragma unroll
        for (int f = 0; f < 2; f++) {
            mx[f][0] = fmaxf(fmaxf(rmx[rg][f][0][lr], rmx[rg][f][1][lr]),
                             fmaxf(rmx[rg][f][2][lr], rmx[rg][f][3][lr]));
            mx[f][1] = fmaxf(fmaxf(rmx[rg][f][0][lr + 8], rmx[rg][f][1][lr + 8]),
                             fmaxf(rmx[rg][f][2][lr + 8], rmx[rg][f][3][lr + 8]));
        }

        if (g == 0 && l4 == 0) {
            int rbase = t0 + rg * 32;
            if (rbase + lr < len) msl += mx[0][0];
            if (rbase + lr + 8 < len) msl += mx[0][1];
            if (rbase + 16 + lr < len) msl += mx[1][0];
            if (rbase + 16 + lr + 8 < len) msl += mx[1][1];
        }

        // exp + pack
        unsigned ue[2][8][2];
#pragma unroll
        for (int f = 0; f < 2; f++)
#pragma unroll
            for (int q = 0; q < 8; q++) {
                ue[f][q][0] = packh2(__expf(c[f][q][0] - mx[f][0]), __expf(c[f][q][1] - mx[f][0]));
                ue[f][q][1] = packh2(__expf(c[f][q][2] - mx[f][1]), __expf(c[f][q][3] - mx[f][1]));
            }

#pragma unroll
        for (int phase = 0; phase < 2; phase++) {
            if (rg == phase) {
#pragma unroll
                for (int f = 0; f < 2; f++) {
                    int r0f = f * 16 + lr;
#pragma unroll
                    for (int q = 0; q < 8; q++) {
                        int wv = g * 32 + q * 4 + l4;
                        stg[r0f * 132 + SWZ(wv)] = ue[f][q][0];
                        stg[(r0f + 8) * 132 + SWZ(wv)] = ue[f][q][1];
                    }
                }
            }
            __syncthreads();   // staging ready

            // copy-out: uniform normal A-fragment layout for ALL rows
            uint4* eo = reinterpret_cast<uint4*>(g_Ep) +
                        ((size_t)b * T_LEN + t0 + 32 * phase) * 32;
            const int w0 = 8 * (lane >> 2) + (lane & 3);
            const int i0 = SWZ(w0), i1 = SWZ(w0 + 64), i2 = SWZ(w0 + 4), i3 = SWZ(w0 + 68);
#pragma unroll
            for (int i = 0; i < 4; i++) {
                int tl = 8 * i + w;
                int base = tl * 132;
                uint4 o;
                o.x = stg[base + i0];
                o.y = stg[base + i1];
                o.z = stg[base + i2];
                o.w = stg[base + i3];
                eo[tl * 32 + lane] = o;
            }
            __syncthreads();   // staging consumed
        }
        buf ^= 1;
    }

    msl = warpSumf(msl);
    if ((w >> 1) == 0 && lane == 0) wsum[w & 1] = msl;
    __syncthreads();
    if (tid == 0) g_msum2[b * 2 + halfb] = wsum[0] + wsum[1];
}

// ---------------- K2: dual-B-operand f16 recursion, warp per b, lag-1 kappa -------------
__global__ void __launch_bounds__(128) k2_fwd(const float* __restrict__ probs_w,
                                              const float* __restrict__ probs_x,
                                              const int* __restrict__ lengths,
                                              const int* __restrict__ mb) {
    const int wid = threadIdx.x >> 5, lane = threadIdx.x & 31;
    const int b = blockIdx.x * 4 + wid;
    const int len = __ldg(&lengths[__ldg(&mb[b])]);

    const int g = lane >> 2, t4 = lane & 3;
    // A-fragments of X^T and W^T:
    //   a0 = M^T[g][2t4..]   = M[2t4..][g]
    //   a1 = M^T[g+8][2t4..] = M[2t4..][g+8]
    //   a2 = M^T[g][2t4+8..] = M[2t4+8..][g]
    //   a3 = M^T[g+8][2t4+8..]
    unsigned XT[4], WT[4];
    XT[0] = packh2(__ldg(&probs_x[(2 * t4) * 16 + g]),         __ldg(&probs_x[(2 * t4 + 1) * 16 + g]));
    XT[1] = packh2(__ldg(&probs_x[(2 * t4) * 16 + g + 8]),     __ldg(&probs_x[(2 * t4 + 1) * 16 + g + 8]));
    XT[2] = packh2(__ldg(&probs_x[(2 * t4 + 8) * 16 + g]),     __ldg(&probs_x[(2 * t4 + 9) * 16 + g]));
    XT[3] = packh2(__ldg(&probs_x[(2 * t4 + 8) * 16 + g + 8]), __ldg(&probs_x[(2 * t4 + 9) * 16 + g + 8]));
    WT[0] = packh2(__ldg(&probs_w[(2 * t4) * 16 + g]),         __ldg(&probs_w[(2 * t4 + 1) * 16 + g]));
    WT[1] = packh2(__ldg(&probs_w[(2 * t4) * 16 + g + 8]),     __ldg(&probs_w[(2 * t4 + 1) * 16 + g + 8]));
    WT[2] = packh2(__ldg(&probs_w[(2 * t4 + 8) * 16 + g]),     __ldg(&probs_w[(2 * t4 + 9) * 16 + g]));
    WT[3] = packh2(__ldg(&probs_w[(2 * t4 + 8) * 16 + g + 8]), __ldg(&probs_w[(2 * t4 + 9) * 16 + g + 8]));

    const uint4* ep = reinterpret_cast<const uint4*>(g_Ep) + (size_t)b * T_LEN * 32 + lane;
    const int bn = 16 * g + 2 * t4;

    unsigned Z[4];
    float C;
    {
        uint4 e0 = ep[0];   // t=0: normal layout
        float2 a0p = *reinterpret_cast<const float2*>(g_a0 + bn);
        float2 a1p = *reinterpret_cast<const float2*>(g_a0 + bn + 128);
        float2 a2p = *reinterpret_cast<const float2*>(g_a0 + bn + 8);
        float2 a3p = *reinterpret_cast<const float2*>(g_a0 + bn + 136);
        float2 e0p = __half22float2(u2h(e0.x));
        float2 e1p = __half22float2(u2h(e0.y));
        float2 e2p = __half22float2(u2h(e0.z));
        float2 e3p = __half22float2(u2h(e0.w));
        float p0x = a0p.x * e0p.x, p0y = a0p.y * e0p.y;
        float p1x = a1p.x * e1p.x, p1y = a1p.y * e1p.y;
        float p2x = a2p.x * e2p.x, p2y = a2p.y * e2p.y;
        float p3x = a3p.x * e3p.x, p3y = a3p.y * e3p.y;
        float s0 = ((p0x + p0y) + (p1x + p1y)) + ((p2x + p2y) + (p3x + p3y));
        s0 = warpSumf(s0);
        float kap0 = __fdividef(1024.0f, s0);
        C = -__logf(kap0);
        Z[0] = packh2(p0x * kap0, p0y * kap0);
        Z[1] = packh2(p1x * kap0, p1y * kap0);
        Z[2] = packh2(p2x * kap0, p2y * kap0);
        Z[3] = packh2(p3x * kap0, p3y * kap0);
    }

    __half2 kap2 = __half2half2(__float2half_rn(1.0f));
    float lk = 0.0f;

    uint4 EA[8];
#pragma unroll
    for (int u = 0; u < 8; u++) EA[u] = ep[(size_t)min(1 + u, len - 1) * 32];

    int t = 1;
    for (; t + 7 < len; t += 8) {
#pragma unroll
        for (int j = 0; j < 8; j++) {
            stepZ_d(Z, C, EA[j], XT, WT, kap2, lk);
            EA[j] = ep[(size_t)min(t + 8 + j, len - 1) * 32];
        }
    }
    for (int j = 0; t < len; t++, j++) stepZ_d(Z, C, EA[j], XT, WT, kap2, lk);

    float2 f0 = __half22float2(u2h(Z[0]));
    float2 f1 = __half22float2(u2h(Z[1]));
    float2 f2 = __half22float2(u2h(Z[2]));
    float2 f3 = __half22float2(u2h(Z[3]));
    float s = ((f0.x + f0.y) + (f1.x + f1.y)) + ((f2.x + f2.y) + (f3.x + f3.y));
    s = warpSumf(s);
    C += __logf(s);
    if (lane == 0) g_C[b] = C;
}

// ---------------- K4: final sum ----------------
__global__ void k4_sum(float* __restrict__ out) {
    __shared__ float red[8];
    const int lane = threadIdx.x & 31;
    const int w0 = threadIdx.x >> 5;
    float acc = 0.0f;
    for (int b = threadIdx.x; b < BATCH; b += 256)
        acc += g_C[b] + g_msum2[2 * b] + g_msum2[2 * b + 1];
    acc = warpSumf(acc);
    if (lane == 0) red[w0] = acc;
    __syncthreads();
    if (threadIdx.x == 0) {
        float s = red[0];
#pragma unroll
        for (int w = 1; w < 8; w++) s += red[w];
        out[0] = s;
    }
}

// ---------------- launch ----------------
extern "C" void kernel_launch(void* const* d_in, const int* in_sizes, int n_in,
                              void* d_out, int out_size) {
    const float* seq     = (const float*)d_in[0];
    const float* probs_w = (const float*)d_in[1];
    const float* probs_x = (const float*)d_in[2];
    const float* w_init  = (const float*)d_in[3];
    const float* x_init  = (const float*)d_in[4];
    const float* probs_y = (const float*)d_in[5];
    const int*   lengths = (const int*)d_in[6];
    const int*   mb      = (const int*)d_in[7];
    float* out = (float*)d_out;

    cudaFuncSetAttribute(k1f_emis, cudaFuncAttributeMaxDynamicSharedMemorySize, SM_TOT);

    k0_setup<<<K2ST, 128>>>(probs_y, w_init, x_init);
    k0b_conv<<<dim3(BATCH, 4), 256>>>(seq, lengths, mb);
    k1f_emis<<<dim3(BATCH, 2), 256, SM_TOT>>>(lengths, mb);
    k2_fwd<<<BATCH / 4, 128>>>(probs_w, probs_x, lengths, mb);
    k4_sum<<<1, 256>>>(out);
}